// round 3
// baseline (speedup 1.0000x reference)
#include <cuda_runtime.h>
#include <math_constants.h>

#define BATCH  4
#define SEQ    2048
#define DIM    1024
#define NHEADS 16
#define HDIM   64
#define MROWS  (BATCH*SEQ)   // 8192

// ---------------------------------------------------------------------------
// Scratch (no cudaMalloc allowed)
// ---------------------------------------------------------------------------
__device__ float g_Q[(size_t)MROWS * DIM];
__device__ float g_K[(size_t)MROWS * DIM];
__device__ float g_V[(size_t)MROWS * DIM];
__device__ float g_C[(size_t)MROWS * DIM];

// ---------------------------------------------------------------------------
// tf32 helpers
// ---------------------------------------------------------------------------
__device__ __forceinline__ unsigned f2tf(float x) {
    unsigned r;
    asm("cvt.rna.tf32.f32 %0, %1;" : "=r"(r) : "f"(x));
    return r;
}
__device__ __forceinline__ float tf32r(float x) { return __uint_as_float(f2tf(x)); }
__device__ __forceinline__ unsigned fu(float x)  { return __float_as_uint(x); }

__device__ __forceinline__ void mma8(float c[4], const unsigned a[4], const unsigned b[2]) {
    asm volatile(
        "mma.sync.aligned.m16n8k8.row.col.f32.tf32.tf32.f32 "
        "{%0,%1,%2,%3}, {%4,%5,%6,%7}, {%8,%9}, {%0,%1,%2,%3};\n"
        : "+f"(c[0]), "+f"(c[1]), "+f"(c[2]), "+f"(c[3])
        : "r"(a[0]), "r"(a[1]), "r"(a[2]), "r"(a[3]), "r"(b[0]), "r"(b[1]));
}

// ---------------------------------------------------------------------------
// Pipelined tensor-core GEMM: C = A@B (+bias). Block 128x128, K-step 32,
// double-buffered smem, register prefetch of the next K tile.
// ---------------------------------------------------------------------------
#define GAS 36
#define GBS 132
#define GA_SZ (128*GAS)   // 4608 floats
#define GB_SZ (32*GBS)    // 4224 floats
#define GEMM_SMEM ((2*(GA_SZ+GB_SZ))*4)   // 70656 bytes

template<bool BIAS>
__global__ __launch_bounds__(256)
void gemm_tc(const float* __restrict__ A, const float* __restrict__ B,
             const float* __restrict__ bias, float* __restrict__ C,
             int M, int N, int K)
{
    extern __shared__ float sg[];
    float* Abase = sg;                 // [2][128][GAS]
    float* Bbase = sg + 2 * GA_SZ;     // [2][32][GBS]

    const int t    = threadIdx.x;
    const int warp = t >> 5, lane = t & 31;
    const int lr   = lane >> 2, lc = lane & 3;
    const int wm   = (warp >> 1) << 5;
    const int wn   = (warp & 1) << 6;
    const int row0 = blockIdx.y << 7, col0 = blockIdx.x << 7;

    float acc[2][8][4];
#pragma unroll
    for (int mt = 0; mt < 2; mt++)
#pragma unroll
        for (int nt = 0; nt < 8; nt++)
#pragma unroll
            for (int i = 0; i < 4; i++) acc[mt][nt][i] = 0.f;

    const int ar = t >> 3, ac = (t & 7) << 2;
    const int bk = t >> 5, bn = (t & 31) << 2;

    const float* Ag = A + (size_t)(row0 + ar) * K + ac;
    const float* Bg = B + (size_t)bk * N + col0 + bn;

    float4 av[4], bv[4];
#pragma unroll
    for (int p = 0; p < 4; p++) {
        av[p] = *(const float4*)&Ag[(size_t)(p << 5) * K];
        bv[p] = *(const float4*)&Bg[(size_t)(p << 3) * N];
    }
    {   // stage 0 store
        float* As = Abase; float* Bs = Bbase;
#pragma unroll
        for (int p = 0; p < 4; p++) {
            *(float4*)&As[(ar + (p << 5)) * GAS + ac] =
                make_float4(tf32r(av[p].x), tf32r(av[p].y), tf32r(av[p].z), tf32r(av[p].w));
            *(float4*)&Bs[(bk + (p << 3)) * GBS + bn] =
                make_float4(tf32r(bv[p].x), tf32r(bv[p].y), tf32r(bv[p].z), tf32r(bv[p].w));
        }
    }

    const int NIT = K >> 5;
    for (int it = 0; it < NIT; ++it) {
        if (it + 1 < NIT) {
            const int ko = (it + 1) << 5;
#pragma unroll
            for (int p = 0; p < 4; p++) {
                av[p] = *(const float4*)&Ag[(size_t)(p << 5) * K + ko];
                bv[p] = *(const float4*)&Bg[(size_t)((p << 3) + ko) * N];
            }
        }
        __syncthreads();
        const float* As = Abase + (it & 1) * GA_SZ;
        const float* Bs = Bbase + (it & 1) * GB_SZ;

#pragma unroll
        for (int s = 0; s < 4; s++) {
            const int kk = (s << 3) + lc;
            unsigned af[2][4], bf[8][2];
#pragma unroll
            for (int mt = 0; mt < 2; mt++) {
                int m0 = wm + (mt << 4) + lr;
                af[mt][0] = fu(As[m0 * GAS + kk]);
                af[mt][1] = fu(As[(m0 + 8) * GAS + kk]);
                af[mt][2] = fu(As[m0 * GAS + kk + 4]);
                af[mt][3] = fu(As[(m0 + 8) * GAS + kk + 4]);
            }
#pragma unroll
            for (int nt = 0; nt < 8; nt++) {
                int n0 = wn + (nt << 3) + lr;
                bf[nt][0] = fu(Bs[kk * GBS + n0]);
                bf[nt][1] = fu(Bs[(kk + 4) * GBS + n0]);
            }
#pragma unroll
            for (int mt = 0; mt < 2; mt++)
#pragma unroll
                for (int nt = 0; nt < 8; nt++)
                    mma8(acc[mt][nt], af[mt], bf[nt]);
        }

        if (it + 1 < NIT) {
            float* Asn = Abase + ((it + 1) & 1) * GA_SZ;
            float* Bsn = Bbase + ((it + 1) & 1) * GB_SZ;
#pragma unroll
            for (int p = 0; p < 4; p++) {
                *(float4*)&Asn[(ar + (p << 5)) * GAS + ac] =
                    make_float4(tf32r(av[p].x), tf32r(av[p].y), tf32r(av[p].z), tf32r(av[p].w));
                *(float4*)&Bsn[(bk + (p << 3)) * GBS + bn] =
                    make_float4(tf32r(bv[p].x), tf32r(bv[p].y), tf32r(bv[p].z), tf32r(bv[p].w));
            }
        }
    }

#pragma unroll
    for (int nt = 0; nt < 8; nt++) {
        int c = col0 + wn + (nt << 3) + (lc << 1);
        float bx = 0.f, by = 0.f;
        if (BIAS) { bx = bias[c]; by = bias[c + 1]; }
#pragma unroll
        for (int mt = 0; mt < 2; mt++) {
            int r = row0 + wm + (mt << 4) + lr;
            *(float2*)&C[(size_t)r * N + c] =
                make_float2(acc[mt][nt][0] + bx, acc[mt][nt][1] + by);
            *(float2*)&C[(size_t)(r + 8) * N + c] =
                make_float2(acc[mt][nt][2] + bx, acc[mt][nt][3] + by);
        }
    }
}

// ---------------------------------------------------------------------------
// Tensor-core causal flash attention. Block = 128 q-rows, 8 warps (16 rows
// each). Q in A-fragments. Double-buffered K/V smem + register prefetch.
// P C-fragments converted to A-fragments via intra-quad shuffles (no smem).
// ---------------------------------------------------------------------------
#define LK 68
#define LV 72
#define KSZ (64*LK)          // 4352 floats
#define VSZ (64*LV)          // 4608 floats
#define STG (KSZ+VSZ)        // 8960 floats per stage
#define ATT_SMEM (2*STG*4)   // 71680 bytes

__global__ __launch_bounds__(256)
void attn_tc(const float* __restrict__ Q, const float* __restrict__ K,
             const float* __restrict__ V, float* __restrict__ O)
{
    extern __shared__ float sm[];

    const int qt = (gridDim.x - 1) - blockIdx.x;   // largest tiles first
    const int h  = blockIdx.y, b = blockIdx.z;
    const int t    = threadIdx.x;
    const int warp = t >> 5, lane = t & 31;
    const int lr   = lane >> 2, lc = lane & 3;
    const int q0   = qt << 7, w16 = warp << 4;
    const int wrow0 = q0 + w16;

    // ---- stage Q tile (128x64, scaled, tf32) into smem, read A-fragments ----
    const float* Qb = Q + ((size_t)(b * SEQ + q0)) * DIM + h * HDIM;
#pragma unroll
    for (int j = 0; j < 8; j++) {
        int f = t + (j << 8);
        int r = f >> 4, c4 = (f & 15) << 2;
        float4 v = *(const float4*)&Qb[(size_t)r * DIM + c4];
        *(float4*)&sm[r * LK + c4] =
            make_float4(tf32r(v.x * 0.125f), tf32r(v.y * 0.125f),
                        tf32r(v.z * 0.125f), tf32r(v.w * 0.125f));
    }
    __syncthreads();

    unsigned qa[8][4];
#pragma unroll
    for (int s = 0; s < 8; s++) {
        int kk = (s << 3) + lc;
        qa[s][0] = fu(sm[(w16 + lr) * LK + kk]);
        qa[s][1] = fu(sm[(w16 + lr + 8) * LK + kk]);
        qa[s][2] = fu(sm[(w16 + lr) * LK + kk + 4]);
        qa[s][3] = fu(sm[(w16 + lr + 8) * LK + kk + 4]);
    }

    float o[8][4];
#pragma unroll
    for (int nt = 0; nt < 8; nt++)
#pragma unroll
        for (int i = 0; i < 4; i++) o[nt][i] = 0.f;
    float mrow[2] = {-CUDART_INF_F, -CUDART_INF_F};
    float lsum[2] = {0.f, 0.f};

    const float* Kb = K + (size_t)b * SEQ * DIM + h * HDIM;
    const float* Vb = V + (size_t)b * SEQ * DIM + h * HDIM;
    const int last = 2 * qt + 1;

    // prefetch kv tile 0 into regs (each thread: 4 float4 of K, 4 of V)
    const int sr = t >> 4, sc4 = (t & 15) << 2;   // staging row/col
    float4 kreg[4], vreg[4];
    {
        const float* Kt = Kb;
        const float* Vt = Vb;
#pragma unroll
        for (int i = 0; i < 4; i++) {
            kreg[i] = *(const float4*)&Kt[(size_t)(sr + (i << 4)) * DIM + sc4];
            vreg[i] = *(const float4*)&Vt[(size_t)(sr + (i << 4)) * DIM + sc4];
        }
    }
    __syncthreads();   // Q fragment reads complete before overwriting buf0
    {
        float* Ks = sm; float* Vs = sm + KSZ;
#pragma unroll
        for (int i = 0; i < 4; i++) {
            int r = sr + (i << 4);
            *(float4*)&Ks[r * LK + sc4] =
                make_float4(tf32r(kreg[i].x), tf32r(kreg[i].y), tf32r(kreg[i].z), tf32r(kreg[i].w));
            *(float4*)&Vs[r * LV + sc4] =
                make_float4(tf32r(vreg[i].x), tf32r(vreg[i].y), tf32r(vreg[i].z), tf32r(vreg[i].w));
        }
    }

    for (int kt = 0; kt <= last; ++kt) {
        if (kt < last) {
            const float* Kt = Kb + ((size_t)((kt + 1) << 6)) * DIM;
            const float* Vt = Vb + ((size_t)((kt + 1) << 6)) * DIM;
#pragma unroll
            for (int i = 0; i < 4; i++) {
                kreg[i] = *(const float4*)&Kt[(size_t)(sr + (i << 4)) * DIM + sc4];
                vreg[i] = *(const float4*)&Vt[(size_t)(sr + (i << 4)) * DIM + sc4];
            }
        }
        __syncthreads();
        const float* Ks = sm + (kt & 1) * STG;
        const float* Vs = Ks + KSZ;

        if ((kt << 6) <= wrow0 + 15) {   // not fully masked for this warp
            // ---- S = Q K^T ----
            float sc[8][4];
#pragma unroll
            for (int nt = 0; nt < 8; nt++)
#pragma unroll
                for (int i = 0; i < 4; i++) sc[nt][i] = 0.f;
#pragma unroll
            for (int s = 0; s < 8; s++) {
                int kk = (s << 3) + lc;
#pragma unroll
                for (int nt = 0; nt < 8; nt++) {
                    unsigned bf[2];
                    bf[0] = fu(Ks[((nt << 3) + lr) * LK + kk]);
                    bf[1] = fu(Ks[((nt << 3) + lr) * LK + kk + 4]);
                    mma8(sc[nt], qa[s], bf);
                }
            }

            // ---- causal mask ----
            if ((kt << 6) + 63 > wrow0) {
#pragma unroll
                for (int nt = 0; nt < 8; nt++)
#pragma unroll
                    for (int i = 0; i < 4; i++) {
                        int rr = wrow0 + lr + ((i >> 1) << 3);
                        int cc = (kt << 6) + (nt << 3) + (lc << 1) + (i & 1);
                        if (cc > rr) sc[nt][i] = -CUDART_INF_F;
                    }
            }

            // ---- online softmax ----
#pragma unroll
            for (int hh = 0; hh < 2; hh++) {
                const int i0 = hh << 1;
                float rm = -CUDART_INF_F;
#pragma unroll
                for (int nt = 0; nt < 8; nt++)
                    rm = fmaxf(rm, fmaxf(sc[nt][i0], sc[nt][i0 + 1]));
                rm = fmaxf(rm, __shfl_xor_sync(0xffffffffu, rm, 1));
                rm = fmaxf(rm, __shfl_xor_sync(0xffffffffu, rm, 2));
                float mnew  = fmaxf(mrow[hh], rm);
                float alpha = __expf(mrow[hh] - mnew);
                mrow[hh] = mnew;
                float ps = 0.f;
#pragma unroll
                for (int nt = 0; nt < 8; nt++) {
                    float p0 = __expf(sc[nt][i0]     - mnew);
                    float p1 = __expf(sc[nt][i0 + 1] - mnew);
                    sc[nt][i0] = p0; sc[nt][i0 + 1] = p1;
                    ps += p0 + p1;
                }
                ps += __shfl_xor_sync(0xffffffffu, ps, 1);
                ps += __shfl_xor_sync(0xffffffffu, ps, 2);
                lsum[hh] = lsum[hh] * alpha + ps;
#pragma unroll
                for (int nt = 0; nt < 8; nt++) {
                    o[nt][i0]     *= alpha;
                    o[nt][i0 + 1] *= alpha;
                }
            }

            // ---- O += P V (P fragments via intra-quad shuffles) ----
            const int srcA = (lane & ~3) | (lc >> 1);
            const int srcB = srcA + 2;
            const bool odd = (lc & 1);
#pragma unroll
            for (int g = 0; g < 8; g++) {
                float v00 = __shfl_sync(0xffffffffu, sc[g][0], srcA);
                float v01 = __shfl_sync(0xffffffffu, sc[g][1], srcA);
                float v20 = __shfl_sync(0xffffffffu, sc[g][2], srcA);
                float v21 = __shfl_sync(0xffffffffu, sc[g][3], srcA);
                float v02 = __shfl_sync(0xffffffffu, sc[g][0], srcB);
                float v03 = __shfl_sync(0xffffffffu, sc[g][1], srcB);
                float v22 = __shfl_sync(0xffffffffu, sc[g][2], srcB);
                float v23 = __shfl_sync(0xffffffffu, sc[g][3], srcB);
                unsigned pa[4];
                pa[0] = f2tf(odd ? v01 : v00);
                pa[1] = f2tf(odd ? v21 : v20);
                pa[2] = f2tf(odd ? v03 : v02);
                pa[3] = f2tf(odd ? v23 : v22);
                const int kk = (g << 3) + lc;
#pragma unroll
                for (int nt = 0; nt < 8; nt++) {
                    unsigned bf[2];
                    bf[0] = fu(Vs[kk * LV + (nt << 3) + lr]);
                    bf[1] = fu(Vs[(kk + 4) * LV + (nt << 3) + lr]);
                    mma8(o[nt], pa, bf);
                }
            }
        }

        if (kt < last) {
            float* Ksn = sm + ((kt + 1) & 1) * STG;
            float* Vsn = Ksn + KSZ;
#pragma unroll
            for (int i = 0; i < 4; i++) {
                int r = sr + (i << 4);
                *(float4*)&Ksn[r * LK + sc4] =
                    make_float4(tf32r(kreg[i].x), tf32r(kreg[i].y), tf32r(kreg[i].z), tf32r(kreg[i].w));
                *(float4*)&Vsn[r * LV + sc4] =
                    make_float4(tf32r(vreg[i].x), tf32r(vreg[i].y), tf32r(vreg[i].z), tf32r(vreg[i].w));
            }
        }
    }

    // ---- normalize + write ----
    float* Ob = O + ((size_t)(b * SEQ + q0 + w16)) * DIM + h * HDIM;
#pragma unroll
    for (int hh = 0; hh < 2; hh++) {
        float inv = 1.0f / lsum[hh];
        int r = lr + (hh << 3);
#pragma unroll
        for (int nt = 0; nt < 8; nt++) {
            float2 w = make_float2(o[nt][(hh << 1)] * inv, o[nt][(hh << 1) + 1] * inv);
            *(float2*)&Ob[(size_t)r * DIM + (nt << 3) + (lc << 1)] = w;
        }
    }
}

// ---------------------------------------------------------------------------
// Launch
// ---------------------------------------------------------------------------
extern "C" void kernel_launch(void* const* d_in, const int* in_sizes, int n_in,
                              void* d_out, int out_size)
{
    const float* x  = (const float*)d_in[0];
    const float* Wq = (const float*)d_in[1];
    const float* Wk = (const float*)d_in[2];
    const float* Wv = (const float*)d_in[3];
    const float* Wo = (const float*)d_in[4];
    const float* bo = (const float*)d_in[5];
    float* out = (float*)d_out;

    float *qp, *kp, *vp, *cp;
    cudaGetSymbolAddress((void**)&qp, g_Q);
    cudaGetSymbolAddress((void**)&kp, g_K);
    cudaGetSymbolAddress((void**)&vp, g_V);
    cudaGetSymbolAddress((void**)&cp, g_C);

    cudaFuncSetAttribute(gemm_tc<false>, cudaFuncAttributeMaxDynamicSharedMemorySize, GEMM_SMEM);
    cudaFuncSetAttribute(gemm_tc<true>,  cudaFuncAttributeMaxDynamicSharedMemorySize, GEMM_SMEM);
    cudaFuncSetAttribute(attn_tc, cudaFuncAttributeMaxDynamicSharedMemorySize, ATT_SMEM);

    dim3 gg(DIM / 128, MROWS / 128);  // (8, 64)
    gemm_tc<false><<<gg, 256, GEMM_SMEM>>>(x, Wq, nullptr, qp, MROWS, DIM, DIM);
    gemm_tc<false><<<gg, 256, GEMM_SMEM>>>(x, Wk, nullptr, kp, MROWS, DIM, DIM);
    gemm_tc<false><<<gg, 256, GEMM_SMEM>>>(x, Wv, nullptr, vp, MROWS, DIM, DIM);

    dim3 ga(SEQ / 128, NHEADS, BATCH); // (16, 16, 4)
    attn_tc<<<ga, 256, ATT_SMEM>>>(qp, kp, vp, cp);

    gemm_tc<true><<<gg, 256, GEMM_SMEM>>>(cp, Wo, bo, out, MROWS, DIM, DIM);
}

// round 4
// speedup vs baseline: 1.0654x; 1.0654x over previous
#include <cuda_runtime.h>
#include <math_constants.h>

#define BATCH  4
#define SEQ    2048
#define DIM    1024
#define NHEADS 16
#define HDIM   64
#define MROWS  (BATCH*SEQ)   // 8192

__device__ float g_Q[(size_t)MROWS * DIM];
__device__ float g_K[(size_t)MROWS * DIM];
__device__ float g_V[(size_t)MROWS * DIM];
__device__ float g_C[(size_t)MROWS * DIM];

// ---------------------------------------------------------------------------
// helpers
// ---------------------------------------------------------------------------
__device__ __forceinline__ unsigned f2tf(float x) {
    unsigned r;
    asm("cvt.rna.tf32.f32 %0, %1;" : "=r"(r) : "f"(x));
    return r;
}
__device__ __forceinline__ float tf32r(float x) { return __uint_as_float(f2tf(x)); }
__device__ __forceinline__ unsigned fu(float x) { return __float_as_uint(x); }

__device__ __forceinline__ void mma8(float c[4], const unsigned a[4], const unsigned b[2]) {
    asm volatile(
        "mma.sync.aligned.m16n8k8.row.col.f32.tf32.tf32.f32 "
        "{%0,%1,%2,%3}, {%4,%5,%6,%7}, {%8,%9}, {%0,%1,%2,%3};\n"
        : "+f"(c[0]), "+f"(c[1]), "+f"(c[2]), "+f"(c[3])
        : "r"(a[0]), "r"(a[1]), "r"(a[2]), "r"(a[3]), "r"(b[0]), "r"(b[1]));
}

__device__ __forceinline__ void cpa16(unsigned dst, const void* src) {
    asm volatile("cp.async.cg.shared.global [%0], [%1], 16;\n" :: "r"(dst), "l"(src));
}
#define CP_COMMIT asm volatile("cp.async.commit_group;\n" ::: "memory")
#define CP_WAIT0  asm volatile("cp.async.wait_group 0;\n" ::: "memory")

// ---------------------------------------------------------------------------
// cp.async double-buffered tensor-core GEMM. Block 128x128, kstep 32, 8 warps.
// tf32 conversion at fragment load. EPI: 0 = tf32-round out (K/V),
// 1 = scale 0.125 + tf32-round out (Q), 2 = +bias (output proj).
// ---------------------------------------------------------------------------
#define GAS 36
#define GBS 132
#define GA_SZ (128*GAS)
#define GB_SZ (32*GBS)
#define GSTG  (GA_SZ+GB_SZ)
#define GEMM_SMEM (2*GSTG*4)   // 70656 B

template<int EPI>
__global__ __launch_bounds__(256, 2)
void gemm_tc(const float* __restrict__ A, const float* __restrict__ B,
             const float* __restrict__ bias, float* __restrict__ C,
             int M, int N, int K)
{
    extern __shared__ float sg[];

    const int t    = threadIdx.x;
    const int warp = t >> 5, lane = t & 31;
    const int lr   = lane >> 2, lc = lane & 3;
    const int wm   = (warp >> 1) << 5;
    const int wn   = (warp & 1) << 6;
    const int row0 = blockIdx.y << 7, col0 = blockIdx.x << 7;

    float acc[2][8][4];
#pragma unroll
    for (int mt = 0; mt < 2; mt++)
#pragma unroll
        for (int nt = 0; nt < 8; nt++)
#pragma unroll
            for (int i = 0; i < 4; i++) acc[mt][nt][i] = 0.f;

    const int ar = t >> 3, ac = (t & 7) << 2;
    const int bk = t >> 5, bn = (t & 31) << 2;
    const float* Ag = A + (size_t)(row0 + ar) * K + ac;
    const float* Bg = B + (size_t)bk * N + col0 + bn;

    const unsigned s0 = (unsigned)__cvta_generic_to_shared(sg);

    // issue stage 0
#pragma unroll
    for (int p = 0; p < 4; p++) {
        cpa16(s0 + ((ar + (p << 5)) * GAS + ac) * 4,            &Ag[(size_t)(p << 5) * K]);
        cpa16(s0 + (GA_SZ + (bk + (p << 3)) * GBS + bn) * 4,    &Bg[(size_t)(p << 3) * N]);
    }
    CP_COMMIT;

    const int NIT = K >> 5;
    for (int it = 0; it < NIT; ++it) {
        CP_WAIT0;
        __syncthreads();

        if (it + 1 < NIT) {
            const int ko = (it + 1) << 5;
            const unsigned sb = s0 + ((it + 1) & 1) * GSTG * 4;
#pragma unroll
            for (int p = 0; p < 4; p++) {
                cpa16(sb + ((ar + (p << 5)) * GAS + ac) * 4,         &Ag[(size_t)(p << 5) * K + ko]);
                cpa16(sb + (GA_SZ + (bk + (p << 3)) * GBS + bn) * 4, &Bg[(size_t)((p << 3) + ko) * N]);
            }
            CP_COMMIT;
        }

        const float* As = sg + (it & 1) * GSTG;
        const float* Bs = As + GA_SZ;

#pragma unroll
        for (int s = 0; s < 4; s++) {
            const int kk = (s << 3) + lc;
            unsigned af[2][4], bf[8][2];
#pragma unroll
            for (int mt = 0; mt < 2; mt++) {
                int m0 = wm + (mt << 4) + lr;
                af[mt][0] = f2tf(As[m0 * GAS + kk]);
                af[mt][1] = f2tf(As[(m0 + 8) * GAS + kk]);
                af[mt][2] = f2tf(As[m0 * GAS + kk + 4]);
                af[mt][3] = f2tf(As[(m0 + 8) * GAS + kk + 4]);
            }
#pragma unroll
            for (int nt = 0; nt < 8; nt++) {
                int n0 = wn + (nt << 3) + lr;
                bf[nt][0] = f2tf(Bs[kk * GBS + n0]);
                bf[nt][1] = f2tf(Bs[(kk + 4) * GBS + n0]);
            }
#pragma unroll
            for (int mt = 0; mt < 2; mt++)
#pragma unroll
                for (int nt = 0; nt < 8; nt++)
                    mma8(acc[mt][nt], af[mt], bf[nt]);
        }
    }

#pragma unroll
    for (int nt = 0; nt < 8; nt++) {
        int c = col0 + wn + (nt << 3) + (lc << 1);
        float bx = 0.f, by = 0.f;
        if (EPI == 2) { bx = bias[c]; by = bias[c + 1]; }
#pragma unroll
        for (int mt = 0; mt < 2; mt++) {
            int r = row0 + wm + (mt << 4) + lr;
#pragma unroll
            for (int hh = 0; hh < 2; hh++) {
                float a0 = acc[mt][nt][(hh << 1)], a1 = acc[mt][nt][(hh << 1) + 1];
                float2 w;
                if (EPI == 0)      w = make_float2(tf32r(a0), tf32r(a1));
                else if (EPI == 1) w = make_float2(tf32r(a0 * 0.125f), tf32r(a1 * 0.125f));
                else               w = make_float2(a0 + bx, a1 + by);
                *(float2*)&C[(size_t)(r + (hh << 3)) * N + c] = w;
            }
        }
    }
}

// ---------------------------------------------------------------------------
// Tensor-core causal flash attention. Block = 128 q-rows, 8 warps.
// Q/K/V already tf32-valued (Q pre-scaled) -> zero conversions here.
// K/V staged via cp.async double-buffer. P frags via intra-quad shuffles.
// ---------------------------------------------------------------------------
#define LK 68
#define LV 72
#define KSZ (64*LK)          // 4352 floats
#define VSZ (64*LV)          // 4608 floats
#define STG (KSZ+VSZ)        // 8960 floats / stage
#define ATT_SMEM (2*STG*4)   // 71680 B

__global__ __launch_bounds__(256, 2)
void attn_tc(const float* __restrict__ Q, const float* __restrict__ K,
             const float* __restrict__ V, float* __restrict__ O)
{
    extern __shared__ float sm[];

    const int qt = (gridDim.x - 1) - blockIdx.x;   // largest tiles first
    const int h  = blockIdx.y, b = blockIdx.z;
    const int t    = threadIdx.x;
    const int warp = t >> 5, lane = t & 31;
    const int lr   = lane >> 2, lc = lane & 3;
    const int q0   = qt << 7, w16 = warp << 4;
    const int wrow0 = q0 + w16;

    const float* Kb = K + (size_t)b * SEQ * DIM + h * HDIM;
    const float* Vb = V + (size_t)b * SEQ * DIM + h * HDIM;
    const unsigned smu = (unsigned)__cvta_generic_to_shared(sm);

    // cp.async indices for KV tiles: row kr (0..63), 4 consecutive float4
    const int kr = t >> 2, kc = (t & 3) << 4;   // kc: float offset 0,16,32,48

    // ---- prologue: KV tile 0 -> buf1 (async), Q tile -> buf0 (sync) ----
    {
        const unsigned sb = smu + STG * 4;      // buf1
#pragma unroll
        for (int j = 0; j < 4; j++) {
            cpa16(sb + (kr * LK + kc + (j << 2)) * 4,           &Kb[(size_t)kr * DIM + kc + (j << 2)]);
            cpa16(sb + (KSZ + kr * LV + kc + (j << 2)) * 4,     &Vb[(size_t)kr * DIM + kc + (j << 2)]);
        }
        CP_COMMIT;
    }

    const float* Qb = Q + ((size_t)(b * SEQ + q0)) * DIM + h * HDIM;
#pragma unroll
    for (int j = 0; j < 8; j++) {
        int f = t + (j << 8);
        int r = f >> 4, c4 = (f & 15) << 2;
        *(float4*)&sm[r * LK + c4] = *(const float4*)&Qb[(size_t)r * DIM + c4];
    }
    __syncthreads();

    unsigned qa[8][4];
#pragma unroll
    for (int s = 0; s < 8; s++) {
        int kk = (s << 3) + lc;
        qa[s][0] = fu(sm[(w16 + lr) * LK + kk]);
        qa[s][1] = fu(sm[(w16 + lr + 8) * LK + kk]);
        qa[s][2] = fu(sm[(w16 + lr) * LK + kk + 4]);
        qa[s][3] = fu(sm[(w16 + lr + 8) * LK + kk + 4]);
    }

    float o[8][4];
#pragma unroll
    for (int nt = 0; nt < 8; nt++)
#pragma unroll
        for (int i = 0; i < 4; i++) o[nt][i] = 0.f;
    float mrow[2] = {-CUDART_INF_F, -CUDART_INF_F};
    float lsum[2] = {0.f, 0.f};

    const int last = 2 * qt + 1;

    for (int kt = 0; kt <= last; ++kt) {
        CP_WAIT0;            // KV(kt) landed
        __syncthreads();     // visibility + prior buffer consumers done

        if (kt < last) {     // issue KV(kt+1) into the buffer just freed
            const float* Kt = Kb + ((size_t)((kt + 1) << 6)) * DIM;
            const float* Vt = Vb + ((size_t)((kt + 1) << 6)) * DIM;
            const unsigned sb = smu + (kt & 1) * STG * 4;   // buf_for(kt+1) = kt&1
#pragma unroll
            for (int j = 0; j < 4; j++) {
                cpa16(sb + (kr * LK + kc + (j << 2)) * 4,       &Kt[(size_t)kr * DIM + kc + (j << 2)]);
                cpa16(sb + (KSZ + kr * LV + kc + (j << 2)) * 4, &Vt[(size_t)kr * DIM + kc + (j << 2)]);
            }
            CP_COMMIT;
        }

        const float* Ks = sm + ((kt & 1) ^ 1) * STG;   // buf_for(kt)
        const float* Vs = Ks + KSZ;

        if ((kt << 6) <= wrow0 + 15) {
            // ---- S = Q K^T ----
            float sc[8][4];
#pragma unroll
            for (int nt = 0; nt < 8; nt++)
#pragma unroll
                for (int i = 0; i < 4; i++) sc[nt][i] = 0.f;
#pragma unroll
            for (int s = 0; s < 8; s++) {
                int kk = (s << 3) + lc;
#pragma unroll
                for (int nt = 0; nt < 8; nt++) {
                    unsigned bf[2];
                    bf[0] = fu(Ks[((nt << 3) + lr) * LK + kk]);
                    bf[1] = fu(Ks[((nt << 3) + lr) * LK + kk + 4]);
                    mma8(sc[nt], qa[s], bf);
                }
            }

            // ---- causal mask ----
            if ((kt << 6) + 63 > wrow0) {
#pragma unroll
                for (int nt = 0; nt < 8; nt++)
#pragma unroll
                    for (int i = 0; i < 4; i++) {
                        int rr = wrow0 + lr + ((i >> 1) << 3);
                        int cc = (kt << 6) + (nt << 3) + (lc << 1) + (i & 1);
                        if (cc > rr) sc[nt][i] = -CUDART_INF_F;
                    }
            }

            // ---- online softmax ----
#pragma unroll
            for (int hh = 0; hh < 2; hh++) {
                const int i0 = hh << 1;
                float rm = -CUDART_INF_F;
#pragma unroll
                for (int nt = 0; nt < 8; nt++)
                    rm = fmaxf(rm, fmaxf(sc[nt][i0], sc[nt][i0 + 1]));
                rm = fmaxf(rm, __shfl_xor_sync(0xffffffffu, rm, 1));
                rm = fmaxf(rm, __shfl_xor_sync(0xffffffffu, rm, 2));
                float mnew  = fmaxf(mrow[hh], rm);
                float alpha = __expf(mrow[hh] - mnew);
                mrow[hh] = mnew;
                float ps = 0.f;
#pragma unroll
                for (int nt = 0; nt < 8; nt++) {
                    float p0 = __expf(sc[nt][i0]     - mnew);
                    float p1 = __expf(sc[nt][i0 + 1] - mnew);
                    sc[nt][i0] = p0; sc[nt][i0 + 1] = p1;
                    ps += p0 + p1;
                }
                ps += __shfl_xor_sync(0xffffffffu, ps, 1);
                ps += __shfl_xor_sync(0xffffffffu, ps, 2);
                lsum[hh] = lsum[hh] * alpha + ps;
#pragma unroll
                for (int nt = 0; nt < 8; nt++) {
                    o[nt][i0]     *= alpha;
                    o[nt][i0 + 1] *= alpha;
                }
            }

            // ---- O += P V (P frags via intra-quad shuffles) ----
            const int srcA = (lane & ~3) | (lc >> 1);
            const int srcB = srcA + 2;
            const bool odd = (lc & 1);
#pragma unroll
            for (int g = 0; g < 8; g++) {
                float v00 = __shfl_sync(0xffffffffu, sc[g][0], srcA);
                float v01 = __shfl_sync(0xffffffffu, sc[g][1], srcA);
                float v20 = __shfl_sync(0xffffffffu, sc[g][2], srcA);
                float v21 = __shfl_sync(0xffffffffu, sc[g][3], srcA);
                float v02 = __shfl_sync(0xffffffffu, sc[g][0], srcB);
                float v03 = __shfl_sync(0xffffffffu, sc[g][1], srcB);
                float v22 = __shfl_sync(0xffffffffu, sc[g][2], srcB);
                float v23 = __shfl_sync(0xffffffffu, sc[g][3], srcB);
                unsigned pa[4];
                pa[0] = f2tf(odd ? v01 : v00);
                pa[1] = f2tf(odd ? v21 : v20);
                pa[2] = f2tf(odd ? v03 : v02);
                pa[3] = f2tf(odd ? v23 : v22);
                const int kk = (g << 3) + lc;
#pragma unroll
                for (int nt = 0; nt < 8; nt++) {
                    unsigned bf[2];
                    bf[0] = fu(Vs[kk * LV + (nt << 3) + lr]);
                    bf[1] = fu(Vs[(kk + 4) * LV + (nt << 3) + lr]);
                    mma8(o[nt], pa, bf);
                }
            }
        }
    }

    // ---- normalize + write ----
    float* Ob = O + ((size_t)(b * SEQ + q0 + w16)) * DIM + h * HDIM;
#pragma unroll
    for (int hh = 0; hh < 2; hh++) {
        float inv = 1.0f / lsum[hh];
        int r = lr + (hh << 3);
#pragma unroll
        for (int nt = 0; nt < 8; nt++) {
            float2 w = make_float2(o[nt][(hh << 1)] * inv, o[nt][(hh << 1) + 1] * inv);
            *(float2*)&Ob[(size_t)r * DIM + (nt << 3) + (lc << 1)] = w;
        }
    }
}

// ---------------------------------------------------------------------------
// Launch
// ---------------------------------------------------------------------------
extern "C" void kernel_launch(void* const* d_in, const int* in_sizes, int n_in,
                              void* d_out, int out_size)
{
    const float* x  = (const float*)d_in[0];
    const float* Wq = (const float*)d_in[1];
    const float* Wk = (const float*)d_in[2];
    const float* Wv = (const float*)d_in[3];
    const float* Wo = (const float*)d_in[4];
    const float* bo = (const float*)d_in[5];
    float* out = (float*)d_out;

    float *qp, *kp, *vp, *cp;
    cudaGetSymbolAddress((void**)&qp, g_Q);
    cudaGetSymbolAddress((void**)&kp, g_K);
    cudaGetSymbolAddress((void**)&vp, g_V);
    cudaGetSymbolAddress((void**)&cp, g_C);

    cudaFuncSetAttribute(gemm_tc<0>, cudaFuncAttributeMaxDynamicSharedMemorySize, GEMM_SMEM);
    cudaFuncSetAttribute(gemm_tc<1>, cudaFuncAttributeMaxDynamicSharedMemorySize, GEMM_SMEM);
    cudaFuncSetAttribute(gemm_tc<2>, cudaFuncAttributeMaxDynamicSharedMemorySize, GEMM_SMEM);
    cudaFuncSetAttribute(attn_tc, cudaFuncAttributeMaxDynamicSharedMemorySize, ATT_SMEM);

    dim3 gg(DIM / 128, MROWS / 128);  // (8, 64)
    gemm_tc<1><<<gg, 256, GEMM_SMEM>>>(x, Wq, nullptr, qp, MROWS, DIM, DIM);
    gemm_tc<0><<<gg, 256, GEMM_SMEM>>>(x, Wk, nullptr, kp, MROWS, DIM, DIM);
    gemm_tc<0><<<gg, 256, GEMM_SMEM>>>(x, Wv, nullptr, vp, MROWS, DIM, DIM);

    dim3 ga(SEQ / 128, NHEADS, BATCH); // (16, 16, 4)
    attn_tc<<<ga, 256, ATT_SMEM>>>(qp, kp, vp, cp);

    gemm_tc<2><<<gg, 256, GEMM_SMEM>>>(cp, Wo, bo, out, MROWS, DIM, DIM);
}

// round 6
// speedup vs baseline: 2.0700x; 1.9430x over previous
#include <cuda_runtime.h>
#include <cuda_fp16.h>
#include <math_constants.h>

#define BATCH  4
#define SEQ    2048
#define DIM    1024
#define NHEADS 16
#define HDIM   64
#define MROWS  (BATCH*SEQ)   // 8192

// ---------------------------------------------------------------------------
// Scratch (no cudaMalloc allowed)
// ---------------------------------------------------------------------------
__device__ __half gh_x [(size_t)MROWS * DIM];
__device__ __half gh_Wq[(size_t)DIM * DIM];
__device__ __half gh_Wk[(size_t)DIM * DIM];
__device__ __half gh_Wv[(size_t)DIM * DIM];
__device__ __half gh_Wo[(size_t)DIM * DIM];
__device__ __half g_Q [(size_t)MROWS * DIM];
__device__ __half g_K [(size_t)MROWS * DIM];
__device__ __half g_V [(size_t)MROWS * DIM];
__device__ __half g_C [(size_t)MROWS * DIM];

// ---------------------------------------------------------------------------
// helpers
// ---------------------------------------------------------------------------
__device__ __forceinline__ void mma16(float c[4], const unsigned a[4], const unsigned b[2]) {
    asm volatile(
        "mma.sync.aligned.m16n8k16.row.col.f32.f16.f16.f32 "
        "{%0,%1,%2,%3}, {%4,%5,%6,%7}, {%8,%9}, {%0,%1,%2,%3};\n"
        : "+f"(c[0]), "+f"(c[1]), "+f"(c[2]), "+f"(c[3])
        : "r"(a[0]), "r"(a[1]), "r"(a[2]), "r"(a[3]), "r"(b[0]), "r"(b[1]));
}
__device__ __forceinline__ void ldmx2t(unsigned& r0, unsigned& r1, unsigned addr) {
    asm volatile("ldmatrix.sync.aligned.m8n8.x2.trans.shared.b16 {%0,%1}, [%2];"
                 : "=r"(r0), "=r"(r1) : "r"(addr));
}
__device__ __forceinline__ void cpa16(unsigned dst, const void* src) {
    asm volatile("cp.async.cg.shared.global [%0], [%1], 16;\n" :: "r"(dst), "l"(src));
}
#define CP_COMMIT asm volatile("cp.async.commit_group;\n" ::: "memory")
#define CP_WAIT0  asm volatile("cp.async.wait_group 0;\n" ::: "memory")

// pack two f32 -> one f16x2 register (single SASS cvt)
__device__ __forceinline__ unsigned packh2(float a, float b) {
    unsigned r;
    asm("cvt.rn.f16x2.f32 %0, %1, %2;" : "=r"(r) : "f"(b), "f"(a));
    return r;
}

// ---------------------------------------------------------------------------
// fp32 -> fp16 conversion (one-time)
// ---------------------------------------------------------------------------
__global__ void f2h(const float* __restrict__ s, __half* __restrict__ d, int n) {
    int i = (blockIdx.x * blockDim.x + threadIdx.x) << 2;
    if (i < n) {
        float4 v = *(const float4*)&s[i];
        *(__half2*)&d[i]     = __floats2half2_rn(v.x, v.y);
        *(__half2*)&d[i + 2] = __floats2half2_rn(v.z, v.w);
    }
}

// ---------------------------------------------------------------------------
// fp16 tensor-core GEMM, cp.async double-buffered. Block 128x128, kstep 32,
// 8 warps (warp 32x64). EPI: 0 half out; 1 half out *0.125; 2 float out +bias.
// ---------------------------------------------------------------------------
#define LAH 40
#define LBH 136
#define A_SZH (128*LAH)      // 5120 halves
#define B_SZH (32*LBH)       // 4352 halves
#define GSTGH (A_SZH+B_SZH)  // 9472 halves
#define GEMM_SMEM (2*GSTGH*2)  // 37888 B

template<int EPI>
__global__ __launch_bounds__(256, 2)
void gemm_h(const __half* __restrict__ A, const __half* __restrict__ B,
            const float* __restrict__ bias, __half* __restrict__ Ch,
            float* __restrict__ Cf, int M, int N, int K)
{
    extern __shared__ __half sh[];
    const int t = threadIdx.x, warp = t >> 5, lane = t & 31;
    const int lr = lane >> 2, lc = lane & 3;
    const int wm = (warp >> 1) << 5, wn = (warp & 1) << 6;
    const int row0 = blockIdx.y << 7, col0 = blockIdx.x << 7;

    float acc[2][8][4];
#pragma unroll
    for (int mt = 0; mt < 2; mt++)
#pragma unroll
        for (int nt = 0; nt < 8; nt++)
#pragma unroll
            for (int i = 0; i < 4; i++) acc[mt][nt][i] = 0.f;

    const unsigned s0 = (unsigned)__cvta_generic_to_shared(sh);
    const int a_r = t >> 1, a_c = (t & 1) << 4;   // halves
    const int b_r = t >> 3, b_c = (t & 7) << 4;
    const __half* Ag = A + (size_t)(row0 + a_r) * K + a_c;
    const __half* Bg = B + (size_t)b_r * N + col0 + b_c;

    // stage 0
    {
        cpa16(s0 + (a_r * LAH + a_c) * 2,               Ag);
        cpa16(s0 + (a_r * LAH + a_c + 8) * 2,           Ag + 8);
        cpa16(s0 + (A_SZH + b_r * LBH + b_c) * 2,       Bg);
        cpa16(s0 + (A_SZH + b_r * LBH + b_c + 8) * 2,   Bg + 8);
        CP_COMMIT;
    }

    const int NIT = K >> 5;
    for (int it = 0; it < NIT; ++it) {
        CP_WAIT0;
        __syncthreads();

        if (it + 1 < NIT) {
            const int ko = (it + 1) << 5;
            const unsigned sb = s0 + ((it + 1) & 1) * GSTGH * 2;
            cpa16(sb + (a_r * LAH + a_c) * 2,             Ag + ko);
            cpa16(sb + (a_r * LAH + a_c + 8) * 2,         Ag + ko + 8);
            cpa16(sb + (A_SZH + b_r * LBH + b_c) * 2,     Bg + (size_t)ko * N);
            cpa16(sb + (A_SZH + b_r * LBH + b_c + 8) * 2, Bg + (size_t)ko * N + 8);
            CP_COMMIT;
        }

        const __half* As = sh + (it & 1) * GSTGH;
        const unsigned bbase = s0 + (it & 1) * GSTGH * 2 + A_SZH * 2;

#pragma unroll
        for (int ch = 0; ch < 2; ch++) {
            const int k0 = ch << 4;
            unsigned af[2][4], bf[8][2];
#pragma unroll
            for (int mt = 0; mt < 2; mt++) {
                const __half* ap = As + (wm + (mt << 4) + lr) * LAH + k0 + (lc << 1);
                af[mt][0] = *(const unsigned*)ap;
                af[mt][1] = *(const unsigned*)(ap + 8 * LAH);
                af[mt][2] = *(const unsigned*)(ap + 8);
                af[mt][3] = *(const unsigned*)(ap + 8 * LAH + 8);
            }
#pragma unroll
            for (int nt = 0; nt < 8; nt++) {
                unsigned addr = bbase + (((k0 + (lane & 15)) * LBH) + wn + (nt << 3)) * 2;
                ldmx2t(bf[nt][0], bf[nt][1], addr);
            }
#pragma unroll
            for (int mt = 0; mt < 2; mt++)
#pragma unroll
                for (int nt = 0; nt < 8; nt++)
                    mma16(acc[mt][nt], af[mt], bf[nt]);
        }
    }

#pragma unroll
    for (int nt = 0; nt < 8; nt++) {
        const int c = col0 + wn + (nt << 3) + (lc << 1);
        float bx = 0.f, by = 0.f;
        if (EPI == 2) { bx = bias[c]; by = bias[c + 1]; }
#pragma unroll
        for (int mt = 0; mt < 2; mt++) {
            const int r = row0 + wm + (mt << 4) + lr;
#pragma unroll
            for (int hh = 0; hh < 2; hh++) {
                float a0 = acc[mt][nt][(hh << 1)], a1 = acc[mt][nt][(hh << 1) + 1];
                if (EPI == 2) {
                    *(float2*)&Cf[(size_t)(r + (hh << 3)) * N + c] =
                        make_float2(a0 + bx, a1 + by);
                } else {
                    if (EPI == 1) { a0 *= 0.125f; a1 *= 0.125f; }
                    *(__half2*)&Ch[(size_t)(r + (hh << 3)) * N + c] =
                        __floats2half2_rn(a0, a1);
                }
            }
        }
    }
}

// ---------------------------------------------------------------------------
// fp16 tensor-core causal flash attention. Block = 128 q-rows, 8 warps.
// Q pre-scaled fp16. K/V cp.async double-buffered. P packs straight from
// C-frags into A-frags (no shuffles). V B-frags via ldmatrix.x2.trans.
// ---------------------------------------------------------------------------
#define LKH 72
#define LVH 72
#define KSZH (64*LKH)          // 4608 halves
#define VSZH (64*LVH)          // 4608 halves
#define STGH (KSZH+VSZH)       // 9216 halves per stage
#define ATT_SMEM (2*STGH*2)    // 36864 B

__global__ __launch_bounds__(256)
void attn_h(const __half* __restrict__ Q, const __half* __restrict__ K,
            const __half* __restrict__ V, __half* __restrict__ O)
{
    extern __shared__ __half sh[];

    const int qt = (gridDim.x - 1) - blockIdx.x;   // largest tiles first
    const int h  = blockIdx.y, b = blockIdx.z;
    const int t    = threadIdx.x;
    const int warp = t >> 5, lane = t & 31;
    const int lr   = lane >> 2, lc = lane & 3;
    const int q0   = qt << 7, w16 = warp << 4;
    const int wrow0 = q0 + w16;

    const __half* Kb = K + (size_t)b * SEQ * DIM + h * HDIM;
    const __half* Vb = V + (size_t)b * SEQ * DIM + h * HDIM;
    const unsigned smu = (unsigned)__cvta_generic_to_shared(sh);

    // KV staging: row kvr (0..63), two 16B chunks at halves kvc, kvc+8
    const int kvr = t >> 2, kvc = (t & 3) << 4;

    // ---- prologue: Q -> buf0, KV0 -> buf1, both via cp.async ----
    {
        const __half* Qb = Q + ((size_t)(b * SEQ + q0)) * DIM + h * HDIM;
#pragma unroll
        for (int j = 0; j < 4; j++) {
            int id = t + (j << 8);           // 0..1023
            int r = id >> 3, c = (id & 7) << 3;
            cpa16(smu + (r * LKH + c) * 2, &Qb[(size_t)r * DIM + c]);
        }
        const unsigned sb = smu + STGH * 2;   // buf1
        cpa16(sb + (kvr * LKH + kvc) * 2,            &Kb[(size_t)kvr * DIM + kvc]);
        cpa16(sb + (kvr * LKH + kvc + 8) * 2,        &Kb[(size_t)kvr * DIM + kvc + 8]);
        cpa16(sb + (KSZH + kvr * LVH + kvc) * 2,     &Vb[(size_t)kvr * DIM + kvc]);
        cpa16(sb + (KSZH + kvr * LVH + kvc + 8) * 2, &Vb[(size_t)kvr * DIM + kvc + 8]);
        CP_COMMIT;
        CP_WAIT0;
    }
    __syncthreads();

    // ---- Q A-fragments from buf0 ----
    unsigned qa[4][4];
#pragma unroll
    for (int ch = 0; ch < 4; ch++) {
        const __half* qp = sh + (w16 + lr) * LKH + (ch << 4) + (lc << 1);
        qa[ch][0] = *(const unsigned*)qp;
        qa[ch][1] = *(const unsigned*)(qp + 8 * LKH);
        qa[ch][2] = *(const unsigned*)(qp + 8);
        qa[ch][3] = *(const unsigned*)(qp + 8 * LKH + 8);
    }

    float o[8][4];
#pragma unroll
    for (int nt = 0; nt < 8; nt++)
#pragma unroll
        for (int i = 0; i < 4; i++) o[nt][i] = 0.f;
    float mrow[2] = {-CUDART_INF_F, -CUDART_INF_F};
    float lsum[2] = {0.f, 0.f};

    const int last = 2 * qt + 1;

    for (int kt = 0; kt <= last; ++kt) {
        CP_WAIT0;            // KV(kt) landed
        __syncthreads();     // everyone done with the buffer being refilled

        if (kt < last) {     // prefetch KV(kt+1) into the freed buffer
            const __half* Kt = Kb + ((size_t)((kt + 1) << 6)) * DIM;
            const __half* Vt = Vb + ((size_t)((kt + 1) << 6)) * DIM;
            const unsigned sb = smu + (kt & 1) * STGH * 2;
            cpa16(sb + (kvr * LKH + kvc) * 2,            &Kt[(size_t)kvr * DIM + kvc]);
            cpa16(sb + (kvr * LKH + kvc + 8) * 2,        &Kt[(size_t)kvr * DIM + kvc + 8]);
            cpa16(sb + (KSZH + kvr * LVH + kvc) * 2,     &Vt[(size_t)kvr * DIM + kvc]);
            cpa16(sb + (KSZH + kvr * LVH + kvc + 8) * 2, &Vt[(size_t)kvr * DIM + kvc + 8]);
            CP_COMMIT;
        }

        const int bsel = (kt & 1) ^ 1;               // buffer holding KV(kt)
        const __half* Ks = sh + bsel * STGH;
        const unsigned vbase = smu + bsel * STGH * 2 + KSZH * 2;

        if ((kt << 6) <= wrow0 + 15) {
            // ---- S = Q K^T ----
            float sc[8][4];
#pragma unroll
            for (int nt = 0; nt < 8; nt++)
#pragma unroll
                for (int i = 0; i < 4; i++) sc[nt][i] = 0.f;
#pragma unroll
            for (int ch = 0; ch < 4; ch++) {
                const int k0 = ch << 4;
#pragma unroll
                for (int nt = 0; nt < 8; nt++) {
                    const __half* kp = Ks + ((nt << 3) + lr) * LKH + k0 + (lc << 1);
                    unsigned bf[2];
                    bf[0] = *(const unsigned*)kp;
                    bf[1] = *(const unsigned*)(kp + 8);
                    mma16(sc[nt], qa[ch], bf);
                }
            }

            // ---- causal mask (diag region only) ----
            if ((kt << 6) + 63 > wrow0) {
#pragma unroll
                for (int nt = 0; nt < 8; nt++)
#pragma unroll
                    for (int i = 0; i < 4; i++) {
                        int rr = wrow0 + lr + ((i >> 1) << 3);
                        int cc = (kt << 6) + (nt << 3) + (lc << 1) + (i & 1);
                        if (cc > rr) sc[nt][i] = -CUDART_INF_F;
                    }
            }

            // ---- online softmax ----
#pragma unroll
            for (int hh = 0; hh < 2; hh++) {
                const int i0 = hh << 1;
                float rm = -CUDART_INF_F;
#pragma unroll
                for (int nt = 0; nt < 8; nt++)
                    rm = fmaxf(rm, fmaxf(sc[nt][i0], sc[nt][i0 + 1]));
                rm = fmaxf(rm, __shfl_xor_sync(0xffffffffu, rm, 1));
                rm = fmaxf(rm, __shfl_xor_sync(0xffffffffu, rm, 2));
                float mnew  = fmaxf(mrow[hh], rm);
                float alpha = __expf(mrow[hh] - mnew);
                mrow[hh] = mnew;
                float ps = 0.f;
#pragma unroll
                for (int nt = 0; nt < 8; nt++) {
                    float p0 = __expf(sc[nt][i0]     - mnew);
                    float p1 = __expf(sc[nt][i0 + 1] - mnew);
                    sc[nt][i0] = p0; sc[nt][i0 + 1] = p1;
                    ps += p0 + p1;
                }
                ps += __shfl_xor_sync(0xffffffffu, ps, 1);
                ps += __shfl_xor_sync(0xffffffffu, ps, 2);
                lsum[hh] = lsum[hh] * alpha + ps;
#pragma unroll
                for (int nt = 0; nt < 8; nt++) {
                    o[nt][i0]     *= alpha;
                    o[nt][i0 + 1] *= alpha;
                }
            }

            // ---- O += P V : pack P C-frags directly into A-frags ----
#pragma unroll
            for (int g = 0; g < 4; g++) {
                unsigned pa[4];
                pa[0] = packh2(sc[2 * g][0],     sc[2 * g][1]);
                pa[1] = packh2(sc[2 * g][2],     sc[2 * g][3]);
                pa[2] = packh2(sc[2 * g + 1][0], sc[2 * g + 1][1]);
                pa[3] = packh2(sc[2 * g + 1][2], sc[2 * g + 1][3]);
#pragma unroll
                for (int nt = 0; nt < 8; nt++) {
                    unsigned addr = vbase + ((((g << 4) + (lane & 15)) * LVH) + (nt << 3)) * 2;
                    unsigned bf[2];
                    ldmx2t(bf[0], bf[1], addr);
                    mma16(o[nt], pa, bf);
                }
            }
        }
    }

    // ---- normalize + write ctx (fp16) ----
    __half* Ob = O + ((size_t)(b * SEQ + q0 + w16)) * DIM + h * HDIM;
#pragma unroll
    for (int hh = 0; hh < 2; hh++) {
        float inv = 1.0f / lsum[hh];
        int r = lr + (hh << 3);
#pragma unroll
        for (int nt = 0; nt < 8; nt++) {
            *(__half2*)&Ob[(size_t)r * DIM + (nt << 3) + (lc << 1)] =
                __floats2half2_rn(o[nt][(hh << 1)] * inv, o[nt][(hh << 1) + 1] * inv);
        }
    }
}

// ---------------------------------------------------------------------------
// Launch
// ---------------------------------------------------------------------------
extern "C" void kernel_launch(void* const* d_in, const int* in_sizes, int n_in,
                              void* d_out, int out_size)
{
    const float* x  = (const float*)d_in[0];
    const float* Wq = (const float*)d_in[1];
    const float* Wk = (const float*)d_in[2];
    const float* Wv = (const float*)d_in[3];
    const float* Wo = (const float*)d_in[4];
    const float* bo = (const float*)d_in[5];
    float* out = (float*)d_out;

    __half *xh, *wqh, *wkh, *wvh, *woh, *qp, *kp, *vp, *cp;
    cudaGetSymbolAddress((void**)&xh,  gh_x);
    cudaGetSymbolAddress((void**)&wqh, gh_Wq);
    cudaGetSymbolAddress((void**)&wkh, gh_Wk);
    cudaGetSymbolAddress((void**)&wvh, gh_Wv);
    cudaGetSymbolAddress((void**)&woh, gh_Wo);
    cudaGetSymbolAddress((void**)&qp,  g_Q);
    cudaGetSymbolAddress((void**)&kp,  g_K);
    cudaGetSymbolAddress((void**)&vp,  g_V);
    cudaGetSymbolAddress((void**)&cp,  g_C);

    const int NX = MROWS * DIM, NW = DIM * DIM;
    f2h<<<NX / 4 / 256, 256>>>(x,  xh,  NX);
    f2h<<<NW / 4 / 256, 256>>>(Wq, wqh, NW);
    f2h<<<NW / 4 / 256, 256>>>(Wk, wkh, NW);
    f2h<<<NW / 4 / 256, 256>>>(Wv, wvh, NW);
    f2h<<<NW / 4 / 256, 256>>>(Wo, woh, NW);

    dim3 gg(DIM / 128, MROWS / 128);  // (8, 64)
    gemm_h<1><<<gg, 256, GEMM_SMEM>>>(xh, wqh, nullptr, qp, nullptr, MROWS, DIM, DIM);
    gemm_h<0><<<gg, 256, GEMM_SMEM>>>(xh, wkh, nullptr, kp, nullptr, MROWS, DIM, DIM);
    gemm_h<0><<<gg, 256, GEMM_SMEM>>>(xh, wvh, nullptr, vp, nullptr, MROWS, DIM, DIM);

    dim3 ga(SEQ / 128, NHEADS, BATCH); // (16, 16, 4)
    attn_h<<<ga, 256, ATT_SMEM>>>(qp, kp, vp, cp);

    gemm_h<2><<<gg, 256, GEMM_SMEM>>>(cp, woh, bo, nullptr, out, MROWS, DIM, DIM);
}

// round 7
// speedup vs baseline: 2.3574x; 1.1389x over previous
#include <cuda_runtime.h>
#include <cuda_fp16.h>
#include <math_constants.h>

#define BATCH  4
#define SEQ    2048
#define DIM    1024
#define NHEADS 16
#define HDIM   64
#define MROWS  (BATCH*SEQ)   // 8192

// ---------------------------------------------------------------------------
// Scratch (no cudaMalloc allowed)
// ---------------------------------------------------------------------------
__device__ __half gh_x [(size_t)MROWS * DIM];
__device__ __half gh_Wq[(size_t)DIM * DIM];
__device__ __half gh_Wk[(size_t)DIM * DIM];
__device__ __half gh_Wv[(size_t)DIM * DIM];
__device__ __half gh_Wo[(size_t)DIM * DIM];
__device__ __half g_Q [(size_t)MROWS * DIM];
__device__ __half g_K [(size_t)MROWS * DIM];
__device__ __half g_V [(size_t)MROWS * DIM];
__device__ __half g_C [(size_t)MROWS * DIM];

// ---------------------------------------------------------------------------
// helpers
// ---------------------------------------------------------------------------
__device__ __forceinline__ void mma16(float c[4], const unsigned a[4], const unsigned b[2]) {
    asm volatile(
        "mma.sync.aligned.m16n8k16.row.col.f32.f16.f16.f32 "
        "{%0,%1,%2,%3}, {%4,%5,%6,%7}, {%8,%9}, {%0,%1,%2,%3};\n"
        : "+f"(c[0]), "+f"(c[1]), "+f"(c[2]), "+f"(c[3])
        : "r"(a[0]), "r"(a[1]), "r"(a[2]), "r"(a[3]), "r"(b[0]), "r"(b[1]));
}
__device__ __forceinline__ void ldmx2t(unsigned& r0, unsigned& r1, unsigned addr) {
    asm volatile("ldmatrix.sync.aligned.m8n8.x2.trans.shared.b16 {%0,%1}, [%2];"
                 : "=r"(r0), "=r"(r1) : "r"(addr));
}
__device__ __forceinline__ void ldmx2(unsigned& r0, unsigned& r1, unsigned addr) {
    asm volatile("ldmatrix.sync.aligned.m8n8.x2.shared.b16 {%0,%1}, [%2];"
                 : "=r"(r0), "=r"(r1) : "r"(addr));
}
__device__ __forceinline__ void ldmx4(unsigned& r0, unsigned& r1, unsigned& r2, unsigned& r3,
                                      unsigned addr) {
    asm volatile("ldmatrix.sync.aligned.m8n8.x4.shared.b16 {%0,%1,%2,%3}, [%4];"
                 : "=r"(r0), "=r"(r1), "=r"(r2), "=r"(r3) : "r"(addr));
}
__device__ __forceinline__ void cpa16(unsigned dst, const void* src) {
    asm volatile("cp.async.cg.shared.global [%0], [%1], 16;\n" :: "r"(dst), "l"(src));
}
#define CP_COMMIT asm volatile("cp.async.commit_group;\n" ::: "memory")
#define CP_WAIT0  asm volatile("cp.async.wait_group 0;\n" ::: "memory")

__device__ __forceinline__ unsigned packh2(float a, float b) {
    unsigned r;
    asm("cvt.rn.f16x2.f32 %0, %1, %2;" : "=r"(r) : "f"(b), "f"(a));
    return r;
}

// ---------------------------------------------------------------------------
// fp32 -> fp16 (one-time). f2h: single array. w4h: the 4 weight matrices.
// ---------------------------------------------------------------------------
__global__ void f2h(const float* __restrict__ s, __half* __restrict__ d, int n) {
    int i = (blockIdx.x * blockDim.x + threadIdx.x) << 2;
    if (i < n) {
        float4 v = *(const float4*)&s[i];
        *(__half2*)&d[i]     = __floats2half2_rn(v.x, v.y);
        *(__half2*)&d[i + 2] = __floats2half2_rn(v.z, v.w);
    }
}
__global__ void w4h(const float* __restrict__ s0, const float* __restrict__ s1,
                    const float* __restrict__ s2, const float* __restrict__ s3,
                    __half* __restrict__ d0, __half* __restrict__ d1,
                    __half* __restrict__ d2, __half* __restrict__ d3) {
    const int g   = blockIdx.x * blockDim.x + threadIdx.x;   // 0 .. DIM*DIM-1
    const int seg = g >> 18;                                  // DIM*DIM/4 = 2^18
    const int i   = (g & 0x3FFFF) << 2;
    const float* s = (seg == 0) ? s0 : (seg == 1) ? s1 : (seg == 2) ? s2 : s3;
    __half*      d = (seg == 0) ? d0 : (seg == 1) ? d1 : (seg == 2) ? d2 : d3;
    float4 v = *(const float4*)&s[i];
    *(__half2*)&d[i]     = __floats2half2_rn(v.x, v.y);
    *(__half2*)&d[i + 2] = __floats2half2_rn(v.z, v.w);
}

// ---------------------------------------------------------------------------
// GEMM tile machinery (shared by fused-QKV and output-proj kernels)
// Block 128x128, kstep 32, 8 warps (warp 32x64), cp.async double-buffered,
// ldmatrix.x4 A-frags, ldmatrix.x2.trans B-frags.
// ---------------------------------------------------------------------------
#define LAH 40
#define LBH 136
#define A_SZH (128*LAH)      // 5120 halves
#define B_SZH (32*LBH)       // 4352 halves
#define GSTGH (A_SZH+B_SZH)  // 9472 halves
#define GEMM_SMEM (2*GSTGH*2)  // 37888 B

struct GemmCtx {
    int t, warp, lane, wm, wn;
    unsigned s0;
};

__device__ __forceinline__ void gemm_mainloop(
    const __half* __restrict__ Ag, const __half* __restrict__ Bg,
    __half* sh, const GemmCtx& cx, float acc[2][8][4])
{
    const int t = cx.t, lane = cx.lane;
    const int a_r = t >> 1, a_c = (t & 1) << 4;
    const int b_r = t >> 3, b_c = (t & 7) << 4;
    const unsigned s0 = cx.s0;

    // stage 0
    cpa16(s0 + (a_r * LAH + a_c) * 2,             Ag);
    cpa16(s0 + (a_r * LAH + a_c + 8) * 2,         Ag + 8);
    cpa16(s0 + (A_SZH + b_r * LBH + b_c) * 2,     Bg);
    cpa16(s0 + (A_SZH + b_r * LBH + b_c + 8) * 2, Bg + 8);
    CP_COMMIT;

    // ldmatrix lane addressing
    const int arow = lane & 15;                 // A: row within 16
    const int akof = (lane & 16) >> 1;          // A: +8 halves for mats 2,3

    const int NIT = DIM >> 5;
    for (int it = 0; it < NIT; ++it) {
        CP_WAIT0;
        __syncthreads();

        if (it + 1 < NIT) {
            const int ko = (it + 1) << 5;
            const unsigned sb = s0 + ((it + 1) & 1) * GSTGH * 2;
            cpa16(sb + (a_r * LAH + a_c) * 2,             Ag + ko);
            cpa16(sb + (a_r * LAH + a_c + 8) * 2,         Ag + ko + 8);
            cpa16(sb + (A_SZH + b_r * LBH + b_c) * 2,     Bg + (size_t)ko * DIM);
            cpa16(sb + (A_SZH + b_r * LBH + b_c + 8) * 2, Bg + (size_t)ko * DIM + 8);
            CP_COMMIT;
        }

        const unsigned abase = s0 + (it & 1) * GSTGH * 2;
        const unsigned bbase = abase + A_SZH * 2;

#pragma unroll
        for (int ch = 0; ch < 2; ch++) {
            const int k0 = ch << 4;
            unsigned af[2][4], bf[8][2];
#pragma unroll
            for (int mt = 0; mt < 2; mt++) {
                unsigned addr = abase +
                    (((cx.wm + (mt << 4) + arow) * LAH) + k0 + akof) * 2;
                ldmx4(af[mt][0], af[mt][1], af[mt][2], af[mt][3], addr);
            }
#pragma unroll
            for (int nt = 0; nt < 8; nt++) {
                unsigned addr = bbase +
                    (((k0 + (lane & 15)) * LBH) + cx.wn + (nt << 3)) * 2;
                ldmx2t(bf[nt][0], bf[nt][1], addr);
            }
#pragma unroll
            for (int mt = 0; mt < 2; mt++)
#pragma unroll
                for (int nt = 0; nt < 8; nt++)
                    mma16(acc[mt][nt], af[mt], bf[nt]);
        }
    }
}

// ---- fused QKV projection: grid (24, 64). blockIdx.x -> {matrix, col-block}
__global__ __launch_bounds__(256, 2)
void gemm_qkv(const __half* __restrict__ xh,
              const __half* __restrict__ Wq, const __half* __restrict__ Wk,
              const __half* __restrict__ Wv,
              __half* __restrict__ Qo, __half* __restrict__ Ko,
              __half* __restrict__ Vo)
{
    extern __shared__ __half sh[];
    GemmCtx cx;
    cx.t = threadIdx.x; cx.warp = cx.t >> 5; cx.lane = cx.t & 31;
    cx.wm = (cx.warp >> 1) << 5; cx.wn = (cx.warp & 1) << 6;
    cx.s0 = (unsigned)__cvta_generic_to_shared(sh);

    const int widx = blockIdx.x >> 3;             // 0=Q 1=K 2=V
    const int col0 = (blockIdx.x & 7) << 7;
    const int row0 = blockIdx.y << 7;
    const __half* B = (widx == 0) ? Wq : (widx == 1) ? Wk : Wv;
    __half*       C = (widx == 0) ? Qo : (widx == 1) ? Ko : Vo;
    const float scale = (widx == 0) ? 0.125f : 1.0f;

    float acc[2][8][4];
#pragma unroll
    for (int mt = 0; mt < 2; mt++)
#pragma unroll
        for (int nt = 0; nt < 8; nt++)
#pragma unroll
            for (int i = 0; i < 4; i++) acc[mt][nt][i] = 0.f;

    const int a_r = cx.t >> 1, a_c = (cx.t & 1) << 4;
    const int b_r = cx.t >> 3, b_c = (cx.t & 7) << 4;
    gemm_mainloop(xh + (size_t)(row0 + a_r) * DIM + a_c,
                  B + (size_t)b_r * DIM + col0 + b_c, sh, cx, acc);

    const int lr = cx.lane >> 2, lc = cx.lane & 3;
#pragma unroll
    for (int nt = 0; nt < 8; nt++) {
        const int c = col0 + cx.wn + (nt << 3) + (lc << 1);
#pragma unroll
        for (int mt = 0; mt < 2; mt++) {
            const int r = row0 + cx.wm + (mt << 4) + lr;
#pragma unroll
            for (int hh = 0; hh < 2; hh++) {
                float a0 = acc[mt][nt][(hh << 1)] * scale;
                float a1 = acc[mt][nt][(hh << 1) + 1] * scale;
                *(__half2*)&C[(size_t)(r + (hh << 3)) * DIM + c] =
                    __floats2half2_rn(a0, a1);
            }
        }
    }
}

// ---- output projection: float out + bias. grid (8, 64)
__global__ __launch_bounds__(256, 2)
void gemm_out(const __half* __restrict__ A, const __half* __restrict__ B,
              const float* __restrict__ bias, float* __restrict__ Cf)
{
    extern __shared__ __half sh[];
    GemmCtx cx;
    cx.t = threadIdx.x; cx.warp = cx.t >> 5; cx.lane = cx.t & 31;
    cx.wm = (cx.warp >> 1) << 5; cx.wn = (cx.warp & 1) << 6;
    cx.s0 = (unsigned)__cvta_generic_to_shared(sh);

    const int col0 = blockIdx.x << 7;
    const int row0 = blockIdx.y << 7;

    float acc[2][8][4];
#pragma unroll
    for (int mt = 0; mt < 2; mt++)
#pragma unroll
        for (int nt = 0; nt < 8; nt++)
#pragma unroll
            for (int i = 0; i < 4; i++) acc[mt][nt][i] = 0.f;

    const int a_r = cx.t >> 1, a_c = (cx.t & 1) << 4;
    const int b_r = cx.t >> 3, b_c = (cx.t & 7) << 4;
    gemm_mainloop(A + (size_t)(row0 + a_r) * DIM + a_c,
                  B + (size_t)b_r * DIM + col0 + b_c, sh, cx, acc);

    const int lr = cx.lane >> 2, lc = cx.lane & 3;
#pragma unroll
    for (int nt = 0; nt < 8; nt++) {
        const int c = col0 + cx.wn + (nt << 3) + (lc << 1);
        const float bx = bias[c], by = bias[c + 1];
#pragma unroll
        for (int mt = 0; mt < 2; mt++) {
            const int r = row0 + cx.wm + (mt << 4) + lr;
#pragma unroll
            for (int hh = 0; hh < 2; hh++) {
                *(float2*)&Cf[(size_t)(r + (hh << 3)) * DIM + c] =
                    make_float2(acc[mt][nt][(hh << 1)] + bx,
                                acc[mt][nt][(hh << 1) + 1] + by);
            }
        }
    }
}

// ---------------------------------------------------------------------------
// fp16 tensor-core causal flash attention. Block = 128 q-rows, 8 warps.
// Q pre-scaled fp16. K/V cp.async double-buffered. K B-frags via non-trans
// ldmatrix.x2 (K stored [n][k]); V via ldmatrix.x2.trans; P packed from
// C-frags directly.
// ---------------------------------------------------------------------------
#define LKH 72
#define LVH 72
#define KSZH (64*LKH)          // 4608 halves
#define VSZH (64*LVH)          // 4608 halves
#define STGH (KSZH+VSZH)       // 9216 halves per stage
#define ATT_SMEM (2*STGH*2)    // 36864 B

__global__ __launch_bounds__(256)
void attn_h(const __half* __restrict__ Q, const __half* __restrict__ K,
            const __half* __restrict__ V, __half* __restrict__ O)
{
    extern __shared__ __half sh[];

    const int qt = (gridDim.x - 1) - blockIdx.x;   // largest tiles first
    const int h  = blockIdx.y, b = blockIdx.z;
    const int t    = threadIdx.x;
    const int warp = t >> 5, lane = t & 31;
    const int lr   = lane >> 2, lc = lane & 3;
    const int q0   = qt << 7, w16 = warp << 4;
    const int wrow0 = q0 + w16;

    const __half* Kb = K + (size_t)b * SEQ * DIM + h * HDIM;
    const __half* Vb = V + (size_t)b * SEQ * DIM + h * HDIM;
    const unsigned smu = (unsigned)__cvta_generic_to_shared(sh);

    const int kvr = t >> 2, kvc = (t & 3) << 4;

    // ---- prologue: Q -> buf0, KV0 -> buf1 ----
    {
        const __half* Qb = Q + ((size_t)(b * SEQ + q0)) * DIM + h * HDIM;
#pragma unroll
        for (int j = 0; j < 4; j++) {
            int id = t + (j << 8);
            int r = id >> 3, c = (id & 7) << 3;
            cpa16(smu + (r * LKH + c) * 2, &Qb[(size_t)r * DIM + c]);
        }
        const unsigned sb = smu + STGH * 2;
        cpa16(sb + (kvr * LKH + kvc) * 2,            &Kb[(size_t)kvr * DIM + kvc]);
        cpa16(sb + (kvr * LKH + kvc + 8) * 2,        &Kb[(size_t)kvr * DIM + kvc + 8]);
        cpa16(sb + (KSZH + kvr * LVH + kvc) * 2,     &Vb[(size_t)kvr * DIM + kvc]);
        cpa16(sb + (KSZH + kvr * LVH + kvc + 8) * 2, &Vb[(size_t)kvr * DIM + kvc + 8]);
        CP_COMMIT;
        CP_WAIT0;
    }
    __syncthreads();

    // ---- Q A-fragments from buf0 (ldmatrix.x4) ----
    unsigned qa[4][4];
    {
        const int arow = lane & 15;
        const int akof = (lane & 16) >> 1;
#pragma unroll
        for (int ch = 0; ch < 4; ch++) {
            unsigned addr = smu + (((w16 + arow) * LKH) + (ch << 4) + akof) * 2;
            ldmx4(qa[ch][0], qa[ch][1], qa[ch][2], qa[ch][3], addr);
        }
    }

    float o[8][4];
#pragma unroll
    for (int nt = 0; nt < 8; nt++)
#pragma unroll
        for (int i = 0; i < 4; i++) o[nt][i] = 0.f;
    float mrow[2] = {-CUDART_INF_F, -CUDART_INF_F};
    float lsum[2] = {0.f, 0.f};

    const int last = 2 * qt + 1;

    for (int kt = 0; kt <= last; ++kt) {
        CP_WAIT0;
        __syncthreads();

        if (kt < last) {
            const __half* Kt = Kb + ((size_t)((kt + 1) << 6)) * DIM;
            const __half* Vt = Vb + ((size_t)((kt + 1) << 6)) * DIM;
            const unsigned sb = smu + (kt & 1) * STGH * 2;
            cpa16(sb + (kvr * LKH + kvc) * 2,            &Kt[(size_t)kvr * DIM + kvc]);
            cpa16(sb + (kvr * LKH + kvc + 8) * 2,        &Kt[(size_t)kvr * DIM + kvc + 8]);
            cpa16(sb + (KSZH + kvr * LVH + kvc) * 2,     &Vt[(size_t)kvr * DIM + kvc]);
            cpa16(sb + (KSZH + kvr * LVH + kvc + 8) * 2, &Vt[(size_t)kvr * DIM + kvc + 8]);
            CP_COMMIT;
        }

        const int bsel = (kt & 1) ^ 1;
        const unsigned kbase = smu + bsel * STGH * 2;
        const unsigned vbase = kbase + KSZH * 2;

        if ((kt << 6) <= wrow0 + 15) {
            // ---- S = Q K^T (K B-frags via non-trans ldmatrix.x2) ----
            float sc[8][4];
#pragma unroll
            for (int nt = 0; nt < 8; nt++)
#pragma unroll
                for (int i = 0; i < 4; i++) sc[nt][i] = 0.f;
#pragma unroll
            for (int ch = 0; ch < 4; ch++) {
                const int k0 = ch << 4;
#pragma unroll
                for (int nt = 0; nt < 8; nt++) {
                    unsigned addr = kbase +
                        ((((nt << 3) + (lane & 7)) * LKH) + k0 + (lane & 8)) * 2;
                    unsigned bf[2];
                    ldmx2(bf[0], bf[1], addr);
                    mma16(sc[nt], qa[ch], bf);
                }
            }

            // ---- causal mask (diag region only) ----
            if ((kt << 6) + 63 > wrow0) {
#pragma unroll
                for (int nt = 0; nt < 8; nt++)
#pragma unroll
                    for (int i = 0; i < 4; i++) {
                        int rr = wrow0 + lr + ((i >> 1) << 3);
                        int cc = (kt << 6) + (nt << 3) + (lc << 1) + (i & 1);
                        if (cc > rr) sc[nt][i] = -CUDART_INF_F;
                    }
            }

            // ---- online softmax ----
#pragma unroll
            for (int hh = 0; hh < 2; hh++) {
                const int i0 = hh << 1;
                float rm = -CUDART_INF_F;
#pragma unroll
                for (int nt = 0; nt < 8; nt++)
                    rm = fmaxf(rm, fmaxf(sc[nt][i0], sc[nt][i0 + 1]));
                rm = fmaxf(rm, __shfl_xor_sync(0xffffffffu, rm, 1));
                rm = fmaxf(rm, __shfl_xor_sync(0xffffffffu, rm, 2));
                float mnew  = fmaxf(mrow[hh], rm);
                float alpha = __expf(mrow[hh] - mnew);
                mrow[hh] = mnew;
                float ps = 0.f;
#pragma unroll
                for (int nt = 0; nt < 8; nt++) {
                    float p0 = __expf(sc[nt][i0]     - mnew);
                    float p1 = __expf(sc[nt][i0 + 1] - mnew);
                    sc[nt][i0] = p0; sc[nt][i0 + 1] = p1;
                    ps += p0 + p1;
                }
                ps += __shfl_xor_sync(0xffffffffu, ps, 1);
                ps += __shfl_xor_sync(0xffffffffu, ps, 2);
                lsum[hh] = lsum[hh] * alpha + ps;
#pragma unroll
                for (int nt = 0; nt < 8; nt++) {
                    o[nt][i0]     *= alpha;
                    o[nt][i0 + 1] *= alpha;
                }
            }

            // ---- O += P V ----
#pragma unroll
            for (int g = 0; g < 4; g++) {
                unsigned pa[4];
                pa[0] = packh2(sc[2 * g][0],     sc[2 * g][1]);
                pa[1] = packh2(sc[2 * g][2],     sc[2 * g][3]);
                pa[2] = packh2(sc[2 * g + 1][0], sc[2 * g + 1][1]);
                pa[3] = packh2(sc[2 * g + 1][2], sc[2 * g + 1][3]);
#pragma unroll
                for (int nt = 0; nt < 8; nt++) {
                    unsigned addr = vbase +
                        ((((g << 4) + (lane & 15)) * LVH) + (nt << 3)) * 2;
                    unsigned bf[2];
                    ldmx2t(bf[0], bf[1], addr);
                    mma16(o[nt], pa, bf);
                }
            }
        }
    }

    // ---- normalize + write ctx (fp16) ----
    __half* Ob = O + ((size_t)(b * SEQ + q0 + w16)) * DIM + h * HDIM;
#pragma unroll
    for (int hh = 0; hh < 2; hh++) {
        float inv = 1.0f / lsum[hh];
        int r = lr + (hh << 3);
#pragma unroll
        for (int nt = 0; nt < 8; nt++) {
            *(__half2*)&Ob[(size_t)r * DIM + (nt << 3) + (lc << 1)] =
                __floats2half2_rn(o[nt][(hh << 1)] * inv, o[nt][(hh << 1) + 1] * inv);
        }
    }
}

// ---------------------------------------------------------------------------
// Launch
// ---------------------------------------------------------------------------
extern "C" void kernel_launch(void* const* d_in, const int* in_sizes, int n_in,
                              void* d_out, int out_size)
{
    const float* x  = (const float*)d_in[0];
    const float* Wq = (const float*)d_in[1];
    const float* Wk = (const float*)d_in[2];
    const float* Wv = (const float*)d_in[3];
    const float* Wo = (const float*)d_in[4];
    const float* bo = (const float*)d_in[5];
    float* out = (float*)d_out;

    __half *xh, *wqh, *wkh, *wvh, *woh, *qp, *kp, *vp, *cp;
    cudaGetSymbolAddress((void**)&xh,  gh_x);
    cudaGetSymbolAddress((void**)&wqh, gh_Wq);
    cudaGetSymbolAddress((void**)&wkh, gh_Wk);
    cudaGetSymbolAddress((void**)&wvh, gh_Wv);
    cudaGetSymbolAddress((void**)&woh, gh_Wo);
    cudaGetSymbolAddress((void**)&qp,  g_Q);
    cudaGetSymbolAddress((void**)&kp,  g_K);
    cudaGetSymbolAddress((void**)&vp,  g_V);
    cudaGetSymbolAddress((void**)&cp,  g_C);

    const int NX = MROWS * DIM, NW = DIM * DIM;
    f2h<<<NX / 4 / 256, 256>>>(x, xh, NX);
    w4h<<<NW / 256, 256>>>(Wq, Wk, Wv, Wo, wqh, wkh, wvh, woh);

    gemm_qkv<<<dim3(24, 64), 256, GEMM_SMEM>>>(xh, wqh, wkh, wvh, qp, kp, vp);

    dim3 ga(SEQ / 128, NHEADS, BATCH); // (16, 16, 4)
    attn_h<<<ga, 256, ATT_SMEM>>>(qp, kp, vp, cp);

    gemm_out<<<dim3(8, 64), 256, GEMM_SMEM>>>(cp, woh, bo, out);
}